// round 1
// baseline (speedup 1.0000x reference)
#include <cuda_runtime.h>
#include <math.h>

// Problem constants
#define Bdim 4
#define Sdim 1024
#define Ddim 512
#define Fdim 2048
#define Hdim 8
#define Edim 8
#define HD 64
#define NTOK 4096        // B*S
#define CAPMAX 256
#define QKVW 1536        // 3*D

// ---------------- scratch (device globals; no allocation) ----------------
__device__ float g_qkv [NTOK * QKVW];          // [N, 3D]
__device__ float g_attn[NTOK * Ddim];          // attention output (pre out-proj)
__device__ float g_aout[NTOK * Ddim];          // after out-proj
__device__ float g_h   [NTOK * Ddim];          // post-LN1 hidden
__device__ float g_moe [NTOK * Ddim];          // scattered MoE output
__device__ float g_hg  [32 * CAPMAX * Ddim];   // gathered tokens per (b,e)
__device__ float g_yg  [32 * CAPMAX * Fdim];   // FFN intermediate
__device__ int   g_idx [NTOK];
__device__ float g_pmax[NTOK];
__device__ int   g_etok[32 * CAPMAX];
__device__ float g_escale[32 * CAPMAX];
__device__ int   g_count[32];

// ---------------- generic zero ----------------
__global__ void zero_kernel(float* __restrict__ p, int n) {
    int i = blockIdx.x * blockDim.x + threadIdx.x;
    if (i < n) p[i] = 0.0f;
}

// ---------------- GEMM NT + bias: C[M,N] = A[M,K] @ B[N,K]^T + bias ----------------
// 128x128 tile, K-chunk 8, 256 threads, 8x8 microtile.
__global__ void __launch_bounds__(256) gemm_nt_bias_kernel(
    const float* __restrict__ A, const float* __restrict__ Bm,
    const float* __restrict__ bias, float* __restrict__ C,
    int M, int N, int K)
{
    __shared__ float As[8][128];
    __shared__ float Bs[8][128];
    const int bm = blockIdx.y * 128;
    const int bn = blockIdx.x * 128;
    const int tid = threadIdx.x;
    const int tx = tid & 15, ty = tid >> 4;
    const int lr = tid >> 1;
    const int lk = (tid & 1) * 4;
    const float* Aptr = A + (size_t)(bm + lr) * K + lk;
    const float* Bptr = Bm + (size_t)(bn + lr) * K + lk;

    float acc[8][8];
#pragma unroll
    for (int i = 0; i < 8; i++)
#pragma unroll
        for (int j = 0; j < 8; j++) acc[i][j] = 0.0f;

    for (int k0 = 0; k0 < K; k0 += 8) {
        float4 av = *(const float4*)(Aptr + k0);
        float4 bv = *(const float4*)(Bptr + k0);
        As[lk + 0][lr] = av.x; As[lk + 1][lr] = av.y;
        As[lk + 2][lr] = av.z; As[lk + 3][lr] = av.w;
        Bs[lk + 0][lr] = bv.x; Bs[lk + 1][lr] = bv.y;
        Bs[lk + 2][lr] = bv.z; Bs[lk + 3][lr] = bv.w;
        __syncthreads();
#pragma unroll
        for (int kk = 0; kk < 8; kk++) {
            float a[8], b[8];
#pragma unroll
            for (int i = 0; i < 8; i++) a[i] = As[kk][ty * 8 + i];
#pragma unroll
            for (int j = 0; j < 8; j++) b[j] = Bs[kk][tx * 8 + j];
#pragma unroll
            for (int i = 0; i < 8; i++)
#pragma unroll
                for (int j = 0; j < 8; j++)
                    acc[i][j] = fmaf(a[i], b[j], acc[i][j]);
        }
        __syncthreads();
    }
#pragma unroll
    for (int i = 0; i < 8; i++) {
        int row = bm + ty * 8 + i;
        float* cp = C + (size_t)row * N + bn + tx * 8;
#pragma unroll
        for (int j = 0; j < 8; j++) cp[j] = acc[i][j] + bias[bn + tx * 8 + j];
    }
}

// ---------------- flash attention (fp32, hd=64) ----------------
// grid (S/64, H, B), 256 threads, q-tile 64, kv-tile 64.
#define FA_SMEM_FLOATS (3 * 64 * 65 + 4 * 64 + 3 * 64)
__global__ void __launch_bounds__(256) flash_attn_kernel(
    const float* __restrict__ qkv, float* __restrict__ out)
{
    extern __shared__ float sm[];
    float* Qs   = sm;                // 64*65
    float* KVs  = Qs + 64 * 65;      // 64*65
    float* Ps   = KVs + 64 * 65;     // 64*65
    float* psum = Ps + 64 * 65;      // 4*64
    float* mrow = psum + 256;        // 64
    float* lrow = mrow + 64;         // 64
    float* arow = lrow + 64;         // 64

    const int qt = blockIdx.x, h = blockIdx.y, b = blockIdx.z;
    const int tid = threadIdx.x;
    const int tx = tid & 15, ty = tid >> 4;
    const int q0 = qt * 64;
    const float scale = 0.125f;   // 1/sqrt(64)

    // load Q tile, pre-scaled
    {
        int r = tid >> 2;
        int c0 = (tid & 3) * 16;
        const float* src = qkv + ((size_t)(b * Sdim + q0 + r)) * QKVW + h * HD + c0;
#pragma unroll
        for (int i = 0; i < 4; i++) {
            float4 v = *(const float4*)(src + 4 * i);
            Qs[r * 65 + c0 + 4 * i + 0] = v.x * scale;
            Qs[r * 65 + c0 + 4 * i + 1] = v.y * scale;
            Qs[r * 65 + c0 + 4 * i + 2] = v.z * scale;
            Qs[r * 65 + c0 + 4 * i + 3] = v.w * scale;
        }
    }
    if (tid < 64) { mrow[tid] = -1e30f; lrow[tid] = 0.0f; }

    float acc[4][4];
#pragma unroll
    for (int i = 0; i < 4; i++)
#pragma unroll
        for (int j = 0; j < 4; j++) acc[i][j] = 0.0f;

    for (int kt = 0; kt < 16; kt++) {
        __syncthreads();   // protect KVs/Ps from previous iteration's readers
        // load K tile
        {
            int r = tid >> 2;
            int c0 = (tid & 3) * 16;
            const float* src = qkv + ((size_t)(b * Sdim + kt * 64 + r)) * QKVW + Ddim + h * HD + c0;
#pragma unroll
            for (int i = 0; i < 4; i++) {
                float4 v = *(const float4*)(src + 4 * i);
                KVs[r * 65 + c0 + 4 * i + 0] = v.x;
                KVs[r * 65 + c0 + 4 * i + 1] = v.y;
                KVs[r * 65 + c0 + 4 * i + 2] = v.z;
                KVs[r * 65 + c0 + 4 * i + 3] = v.w;
            }
        }
        __syncthreads();
        // S = Q @ K^T (scaled)
        float sacc[4][4];
#pragma unroll
        for (int i = 0; i < 4; i++)
#pragma unroll
            for (int j = 0; j < 4; j++) sacc[i][j] = 0.0f;
#pragma unroll 4
        for (int kk = 0; kk < 64; kk++) {
            float qv[4], kv[4];
#pragma unroll
            for (int i = 0; i < 4; i++) qv[i] = Qs[(ty * 4 + i) * 65 + kk];
#pragma unroll
            for (int j = 0; j < 4; j++) kv[j] = KVs[(tx * 4 + j) * 65 + kk];
#pragma unroll
            for (int i = 0; i < 4; i++)
#pragma unroll
                for (int j = 0; j < 4; j++)
                    sacc[i][j] = fmaf(qv[i], kv[j], sacc[i][j]);
        }
#pragma unroll
        for (int i = 0; i < 4; i++)
#pragma unroll
            for (int j = 0; j < 4; j++)
                Ps[(ty * 4 + i) * 65 + tx * 4 + j] = sacc[i][j];
        __syncthreads();
        // load V into KVs (all threads) + running row-max (first 64 threads)
        {
            int r = tid >> 2;
            int c0 = (tid & 3) * 16;
            const float* src = qkv + ((size_t)(b * Sdim + kt * 64 + r)) * QKVW + 2 * Ddim + h * HD + c0;
#pragma unroll
            for (int i = 0; i < 4; i++) {
                float4 v = *(const float4*)(src + 4 * i);
                KVs[r * 65 + c0 + 4 * i + 0] = v.x;
                KVs[r * 65 + c0 + 4 * i + 1] = v.y;
                KVs[r * 65 + c0 + 4 * i + 2] = v.z;
                KVs[r * 65 + c0 + 4 * i + 3] = v.w;
            }
        }
        if (tid < 64) {
            float m = mrow[tid];
#pragma unroll 8
            for (int c = 0; c < 64; c++) m = fmaxf(m, Ps[tid * 65 + c]);
            arow[tid] = __expf(mrow[tid] - m);
            mrow[tid] = m;
        }
        __syncthreads();
        // exp + partial row sums (4 threads per row)
        {
            int row = tid & 63, qq = tid >> 6;
            float m = mrow[row];
            float s = 0.0f;
            int c0 = qq * 16;
#pragma unroll
            for (int c = c0; c < c0 + 16; c++) {
                float p = __expf(Ps[row * 65 + c] - m);
                Ps[row * 65 + c] = p;
                s += p;
            }
            psum[qq * 64 + row] = s;
        }
        __syncthreads();
        if (tid < 64)
            lrow[tid] = arow[tid] * lrow[tid] + psum[tid] + psum[64 + tid] + psum[128 + tid] + psum[192 + tid];
        // rescale accumulator
        {
            float al[4];
#pragma unroll
            for (int i = 0; i < 4; i++) al[i] = arow[ty * 4 + i];
#pragma unroll
            for (int i = 0; i < 4; i++)
#pragma unroll
                for (int j = 0; j < 4; j++) acc[i][j] *= al[i];
        }
        // O += P @ V
#pragma unroll 4
        for (int kk = 0; kk < 64; kk++) {
            float pv[4], vv[4];
#pragma unroll
            for (int i = 0; i < 4; i++) pv[i] = Ps[(ty * 4 + i) * 65 + kk];
#pragma unroll
            for (int j = 0; j < 4; j++) vv[j] = KVs[kk * 65 + tx * 4 + j];
#pragma unroll
            for (int i = 0; i < 4; i++)
#pragma unroll
                for (int j = 0; j < 4; j++)
                    acc[i][j] = fmaf(pv[i], vv[j], acc[i][j]);
        }
    }
    __syncthreads();
    float inv[4];
#pragma unroll
    for (int i = 0; i < 4; i++) inv[i] = 1.0f / lrow[ty * 4 + i];
#pragma unroll
    for (int i = 0; i < 4; i++) {
        float* op = out + ((size_t)(b * Sdim + q0 + ty * 4 + i)) * Ddim + h * HD + tx * 4;
#pragma unroll
        for (int j = 0; j < 4; j++) op[j] = acc[i][j] * inv[i];
    }
}

// ---------------- fused residual add + LayerNorm ----------------
// out[n] = LN(a[n] + r[n]) * g + b ; one block per token, 128 threads
__global__ void __launch_bounds__(128) add_ln_kernel(
    const float* __restrict__ a, const float* __restrict__ r,
    const float* __restrict__ g, const float* __restrict__ be,
    float* __restrict__ out)
{
    const int n = blockIdx.x;
    const int tid = threadIdx.x;
    __shared__ float red[4], red2[4];
    __shared__ float s_mu, s_rstd;
    const float* ap = a + (size_t)n * Ddim;
    const float* rp = r + (size_t)n * Ddim;
    float v[4];
    float sum = 0.0f, sq = 0.0f;
#pragma unroll
    for (int i = 0; i < 4; i++) {
        v[i] = ap[tid + i * 128] + rp[tid + i * 128];
        sum += v[i];
        sq = fmaf(v[i], v[i], sq);
    }
#pragma unroll
    for (int o = 16; o; o >>= 1) {
        sum += __shfl_xor_sync(0xffffffffu, sum, o);
        sq  += __shfl_xor_sync(0xffffffffu, sq, o);
    }
    if ((tid & 31) == 0) { red[tid >> 5] = sum; red2[tid >> 5] = sq; }
    __syncthreads();
    if (tid == 0) {
        float s = red[0] + red[1] + red[2] + red[3];
        float q = red2[0] + red2[1] + red2[2] + red2[3];
        float mu = s * (1.0f / 512.0f);
        float var = q * (1.0f / 512.0f) - mu * mu;
        s_mu = mu;
        s_rstd = rsqrtf(var + 1e-5f);
    }
    __syncthreads();
    float mu = s_mu, rstd = s_rstd;
#pragma unroll
    for (int i = 0; i < 4; i++) {
        int d = tid + i * 128;
        out[(size_t)n * Ddim + d] = (v[i] - mu) * rstd * g[d] + be[d];
    }
}

// ---------------- router: logits + softmax + argmax ----------------
// one warp per token; 8 warps per block
__global__ void __launch_bounds__(256) router_kernel(
    const float* __restrict__ h, const float* __restrict__ rw,
    float* __restrict__ logits_out)
{
    const int w = threadIdx.x >> 5, l = threadIdx.x & 31;
    const int n = blockIdx.x * 8 + w;
    float acc[8];
#pragma unroll
    for (int e = 0; e < 8; e++) acc[e] = 0.0f;
    const float* hp = h + (size_t)n * Ddim;
    for (int d = l; d < Ddim; d += 32) {
        float hv = hp[d];
        const float4* rp = (const float4*)(rw + d * 8);
        float4 r0 = rp[0], r1 = rp[1];
        acc[0] = fmaf(hv, r0.x, acc[0]); acc[1] = fmaf(hv, r0.y, acc[1]);
        acc[2] = fmaf(hv, r0.z, acc[2]); acc[3] = fmaf(hv, r0.w, acc[3]);
        acc[4] = fmaf(hv, r1.x, acc[4]); acc[5] = fmaf(hv, r1.y, acc[5]);
        acc[6] = fmaf(hv, r1.z, acc[6]); acc[7] = fmaf(hv, r1.w, acc[7]);
    }
#pragma unroll
    for (int e = 0; e < 8; e++)
#pragma unroll
        for (int o = 16; o; o >>= 1)
            acc[e] += __shfl_xor_sync(0xffffffffu, acc[e], o);
    if (l == 0) {
        float m = acc[0]; int arg = 0;
#pragma unroll
        for (int e = 1; e < 8; e++) if (acc[e] > m) { m = acc[e]; arg = e; }
        float s = 0.0f;
#pragma unroll
        for (int e = 0; e < 8; e++) s += __expf(acc[e] - m);
#pragma unroll
        for (int e = 0; e < 8; e++) logits_out[(size_t)n * 8 + e] = acc[e];
        g_idx[n] = arg;
        g_pmax[n] = 1.0f / s;   // exp(max-max)/sum
    }
}

// ---------------- capacity scan: per (batch, expert) sequential queue ----------------
__global__ void __launch_bounds__(256) capacity_kernel(
    const int* __restrict__ capp, float* __restrict__ mask_out)
{
    __shared__ int sidx[Sdim];
    __shared__ float spm[Sdim];
    const int b = blockIdx.x, tid = threadIdx.x;
    for (int s = tid; s < Sdim; s += 256) {
        sidx[s] = g_idx[b * Sdim + s];
        spm[s]  = g_pmax[b * Sdim + s];
    }
    __syncthreads();
    if (tid < Edim) {
        const int e = tid;
        int cap = capp[0];
        if (cap > CAPMAX) cap = CAPMAX;
        int cnt = 0;
        const int base = (b * Edim + e) * CAPMAX;
        for (int s = 0; s < Sdim; s++) {
            if (sidx[s] == e) {
                cnt++;
                if (cnt <= cap) {
                    g_etok[base + cnt - 1] = s;
                    g_escale[base + cnt - 1] = spm[s];
                    mask_out[((size_t)(b * Sdim + s)) * Edim + e] = spm[s];
                }
            }
        }
        g_count[b * Edim + e] = cnt < cap ? cnt : cap;
    }
}

// ---------------- gather h rows into packed per-(b,e) buffers ----------------
__global__ void __launch_bounds__(256) gather_kernel()
{
    const int tid = threadIdx.x;
    const int row = blockIdx.x * 4 + (tid >> 6);   // 0..8191
    const int lane = tid & 63;
    const int combo = row >> 8, slot = row & 255;
    float4* dst = (float4*)(g_hg + (size_t)row * Ddim) + lane * 2;
    if (slot < g_count[combo]) {
        const int tok = g_etok[row];
        const int b = combo >> 3;
        const float4* src = (const float4*)(g_h + ((size_t)(b * Sdim + tok)) * Ddim) + lane * 2;
        dst[0] = src[0];
        dst[1] = src[1];
    } else {
        float4 z = {0.f, 0.f, 0.f, 0.f};
        dst[0] = z;
        dst[1] = z;
    }
}

__device__ __forceinline__ float gelu_exact(float x) {
    return 0.5f * x * (1.0f + erff(x * 0.70710678118654752f));
}

// ---------------- MoE FFN1: yg = gelu(hg @ wi[e]) ; NN GEMM, tile skip ----------------
__global__ void __launch_bounds__(256) moe_ffn1_kernel(const float* __restrict__ wi)
{
    const int combo = blockIdx.z;
    const int cnt = g_count[combo];
    if ((int)(blockIdx.y * 128) >= cnt) return;
    const int e = combo & 7;
    const float* A  = g_hg + (size_t)combo * CAPMAX * Ddim;   // [256,512]
    const float* Bm = wi + (size_t)e * Ddim * Fdim;           // [512,2048]
    float* C = g_yg + (size_t)combo * CAPMAX * Fdim;

    __shared__ float As[8][128];
    __shared__ float Bs[8][128];
    const int bm = blockIdx.y * 128;
    const int bn = blockIdx.x * 128;
    const int tid = threadIdx.x;
    const int tx = tid & 15, ty = tid >> 4;
    const int lr = tid >> 1, lk = (tid & 1) * 4;     // A load
    const int kb = tid >> 5, nc = (tid & 31) * 4;    // B load

    float acc[8][8];
#pragma unroll
    for (int i = 0; i < 8; i++)
#pragma unroll
        for (int j = 0; j < 8; j++) acc[i][j] = 0.0f;

    for (int k0 = 0; k0 < Ddim; k0 += 8) {
        float4 av = *(const float4*)(A + (size_t)(bm + lr) * Ddim + k0 + lk);
        float4 bv = *(const float4*)(Bm + (size_t)(k0 + kb) * Fdim + bn + nc);
        As[lk + 0][lr] = av.x; As[lk + 1][lr] = av.y;
        As[lk + 2][lr] = av.z; As[lk + 3][lr] = av.w;
        *(float4*)&Bs[kb][nc] = bv;
        __syncthreads();
#pragma unroll
        for (int kk = 0; kk < 8; kk++) {
            float a[8], b[8];
#pragma unroll
            for (int i = 0; i < 8; i++) a[i] = As[kk][ty * 8 + i];
#pragma unroll
            for (int j = 0; j < 8; j++) b[j] = Bs[kk][tx * 8 + j];
#pragma unroll
            for (int i = 0; i < 8; i++)
#pragma unroll
                for (int j = 0; j < 8; j++)
                    acc[i][j] = fmaf(a[i], b[j], acc[i][j]);
        }
        __syncthreads();
    }
#pragma unroll
    for (int i = 0; i < 8; i++) {
        float* cp = C + (size_t)(bm + ty * 8 + i) * Fdim + bn + tx * 8;
#pragma unroll
        for (int j = 0; j < 8; j++) cp[j] = gelu_exact(acc[i][j]);
    }
}

// ---------------- MoE FFN2: scatter( (yg @ wo[e]) * scale ) into g_moe ----------------
__global__ void __launch_bounds__(256) moe_ffn2_kernel(const float* __restrict__ wo)
{
    const int combo = blockIdx.z;
    const int cnt = g_count[combo];
    if ((int)(blockIdx.y * 128) >= cnt) return;
    const int e = combo & 7;
    const int b = combo >> 3;
    const float* A  = g_yg + (size_t)combo * CAPMAX * Fdim;   // [256,2048]
    const float* Bm = wo + (size_t)e * Fdim * Ddim;           // [2048,512]

    __shared__ float As[8][128];
    __shared__ float Bs[8][128];
    const int bm = blockIdx.y * 128;
    const int bn = blockIdx.x * 128;
    const int tid = threadIdx.x;
    const int tx = tid & 15, ty = tid >> 4;
    const int lr = tid >> 1, lk = (tid & 1) * 4;
    const int kb = tid >> 5, nc = (tid & 31) * 4;

    float acc[8][8];
#pragma unroll
    for (int i = 0; i < 8; i++)
#pragma unroll
        for (int j = 0; j < 8; j++) acc[i][j] = 0.0f;

    for (int k0 = 0; k0 < Fdim; k0 += 8) {
        float4 av = *(const float4*)(A + (size_t)(bm + lr) * Fdim + k0 + lk);
        float4 bv = *(const float4*)(Bm + (size_t)(k0 + kb) * Ddim + bn + nc);
        As[lk + 0][lr] = av.x; As[lk + 1][lr] = av.y;
        As[lk + 2][lr] = av.z; As[lk + 3][lr] = av.w;
        *(float4*)&Bs[kb][nc] = bv;
        __syncthreads();
#pragma unroll
        for (int kk = 0; kk < 8; kk++) {
            float a[8], b[8];
#pragma unroll
            for (int i = 0; i < 8; i++) a[i] = As[kk][ty * 8 + i];
#pragma unroll
            for (int j = 0; j < 8; j++) b[j] = Bs[kk][tx * 8 + j];
#pragma unroll
            for (int i = 0; i < 8; i++)
#pragma unroll
                for (int j = 0; j < 8; j++)
                    acc[i][j] = fmaf(a[i], b[j], acc[i][j]);
        }
        __syncthreads();
    }
#pragma unroll
    for (int i = 0; i < 8; i++) {
        const int m = bm + ty * 8 + i;
        if (m < cnt) {
            const int tok = g_etok[combo * CAPMAX + m];
            const float sc = g_escale[combo * CAPMAX + m];
            float* op = g_moe + ((size_t)(b * Sdim + tok)) * Ddim + bn + tx * 8;
#pragma unroll
            for (int j = 0; j < 8; j++) op[j] = sc * acc[i][j];
        }
    }
}

// ---------------- launch ----------------
extern "C" void kernel_launch(void* const* d_in, const int* in_sizes, int n_in,
                              void* d_out, int out_size)
{
    const float* x     = (const float*)d_in[0];
    const float* in_w  = (const float*)d_in[1];
    const float* in_b  = (const float*)d_in[2];
    const float* out_w = (const float*)d_in[3];
    const float* out_b = (const float*)d_in[4];
    const float* ln1g  = (const float*)d_in[5];
    const float* ln1b  = (const float*)d_in[6];
    const float* ln2g  = (const float*)d_in[7];
    const float* ln2b  = (const float*)d_in[8];
    const float* rw    = (const float*)d_in[9];
    const float* wi    = (const float*)d_in[10];
    const float* wo    = (const float*)d_in[11];
    const int*   cap   = (const int*)d_in[12];

    float* out        = (float*)d_out;                      // [N, D]
    float* logits_out = out + (size_t)NTOK * Ddim;          // [N, E]
    float* mask_out   = logits_out + (size_t)NTOK * Edim;   // [N, E]

    float *p_qkv, *p_attn, *p_aout, *p_h, *p_moe;
    cudaGetSymbolAddress((void**)&p_qkv,  g_qkv);
    cudaGetSymbolAddress((void**)&p_attn, g_attn);
    cudaGetSymbolAddress((void**)&p_aout, g_aout);
    cudaGetSymbolAddress((void**)&p_h,    g_h);
    cudaGetSymbolAddress((void**)&p_moe,  g_moe);

    const int fa_smem = FA_SMEM_FLOATS * (int)sizeof(float);
    cudaFuncSetAttribute(flash_attn_kernel,
                         cudaFuncAttributeMaxDynamicSharedMemorySize, fa_smem);

    // 1) QKV projection: [4096,512] @ [1536,512]^T
    gemm_nt_bias_kernel<<<dim3(QKVW / 128, NTOK / 128), 256>>>(
        x, in_w, in_b, p_qkv, NTOK, QKVW, Ddim);

    // 2) fused attention
    flash_attn_kernel<<<dim3(Sdim / 64, Hdim, Bdim), 256, fa_smem>>>(p_qkv, p_attn);

    // 3) output projection
    gemm_nt_bias_kernel<<<dim3(Ddim / 128, NTOK / 128), 256>>>(
        p_attn, out_w, out_b, p_aout, NTOK, Ddim, Ddim);

    // 4) h = LN1(x + attn_out)
    add_ln_kernel<<<NTOK, 128>>>(p_aout, x, ln1g, ln1b, p_h);

    // 5) zero moe accumulation buffer and expert-mask output region
    zero_kernel<<<(NTOK * Ddim + 255) / 256, 256>>>(p_moe, NTOK * Ddim);
    zero_kernel<<<(NTOK * Edim + 255) / 256, 256>>>(mask_out, NTOK * Edim);

    // 6) router logits / probs / argmax
    router_kernel<<<NTOK / 8, 256>>>(p_h, rw, logits_out);

    // 7) per-(batch,expert) capacity scan -> dispatch lists + mask
    capacity_kernel<<<Bdim, 256>>>(cap, mask_out);

    // 8) gather routed tokens
    gather_kernel<<<(32 * CAPMAX) / 4, 256>>>();

    // 9) expert FFN
    moe_ffn1_kernel<<<dim3(Fdim / 128, CAPMAX / 128, 32), 256>>>(wi);
    moe_ffn2_kernel<<<dim3(Ddim / 128, CAPMAX / 128, 32), 256>>>(wo);

    // 10) out = LN2(h + moe)
    add_ln_kernel<<<NTOK, 128>>>(p_moe, p_h, ln2g, ln2b, out);
}